// round 16
// baseline (speedup 1.0000x reference)
#include <cuda_runtime.h>
#include <math.h>

#define B_   2
#define T_   2048
#define C_   896
#define H_   14
#define HKV_ 2
#define D_   64
#define M_   (B_*T_)          // 4096
#define REP_ (H_/HKV_)        // 7

// ---------------- static scratch ----------------
// g_q: tf32 bits pre-scaled by 0.125*log2(e); g_k: tf32 bits.
// g_vT: V^T tf32 bits [b,hkv,d,t] with t permuted within 8-groups.
// g_att: tf32 bits (converted in attn epilogue for gemm1).
__device__ float    g_q  [(size_t)B_*H_*T_*D_];    // [B,H,T,D]
__device__ float    g_k  [(size_t)B_*HKV_*T_*D_];  // [B,HKV,T,D]
__device__ unsigned g_vT [(size_t)B_*HKV_*D_*T_];  // [B,HKV,D,T']
__device__ float    g_att[(size_t)B_*T_*C_];       // [B,T,H*D] tf32 bits

// ---------------- helpers ----------------
__device__ __forceinline__ unsigned f2tf(float f) {
    unsigned u;
    asm("cvt.rna.tf32.f32 %0, %1;" : "=r"(u) : "f"(f));
    return u;
}
__device__ __forceinline__ float ex2f(float x) {
    float r;
    asm("ex2.approx.f32 %0, %1;" : "=f"(r) : "f"(x));
    return r;
}
__device__ __forceinline__ unsigned sptr(const void* p) {
    return (unsigned)__cvta_generic_to_shared(p);
}
__device__ __forceinline__ void cpasync16(unsigned smem_addr, const void* gptr) {
    asm volatile("cp.async.cg.shared.global [%0], [%1], 16;"
                 :: "r"(smem_addr), "l"(gptr));
}
#define CP_COMMIT() asm volatile("cp.async.commit_group;" ::: "memory")
#define CP_WAIT0()  asm volatile("cp.async.wait_group 0;" ::: "memory")
#define CP_WAIT1()  asm volatile("cp.async.wait_group 1;" ::: "memory")

__device__ __forceinline__ void ldsm4(unsigned& r0, unsigned& r1,
                                      unsigned& r2, unsigned& r3, unsigned a) {
    asm volatile("ldmatrix.sync.aligned.m8n8.x4.shared.b16 {%0,%1,%2,%3}, [%4];"
                 : "=r"(r0), "=r"(r1), "=r"(r2), "=r"(r3) : "r"(a));
}
__device__ __forceinline__ void mma_tf32(float c[4],
                                         const unsigned a[4],
                                         unsigned b0, unsigned b1)
{
    asm volatile("mma.sync.aligned.m16n8k8.row.col.f32.tf32.tf32.f32 "
                 "{%0,%1,%2,%3}, {%4,%5,%6,%7}, {%8,%9}, {%0,%1,%2,%3};"
                 : "+f"(c[0]), "+f"(c[1]), "+f"(c[2]), "+f"(c[3])
                 : "r"(a[0]), "r"(a[1]), "r"(a[2]), "r"(a[3]), "r"(b0), "r"(b1));
}

// warp n-column map: warp wn owns cols {wn*16..+15} U {32+wn*16..+15}
__device__ __forceinline__ int ncol_map(int wn, int nt) {
    return wn*16 + (nt & 1)*8 + (nt >> 1)*32;
}

// =====================================================================
// GEMM kernel (R14 structure).
// MODE 0 = QKV proj, fused bias + RoPE; q/k stored as TF32 BITS
//          (q pre-scaled by 0.125*log2e); V stored TRANSPOSED+PERMUTED
//          tf32 bits into g_vT for attn's cp.async staging.
// MODE 1 = WO (A = g_att tf32 BITS; fp32 out).
// Block 128x64, 8 warps, warp 32x32 (n-columns per ncol_map).
// =====================================================================
template<int MODE>
__global__ __launch_bounds__(256, 2)
void gemm_kernel(const float* __restrict__ Aa,
                 const float* __restrict__ wq, const float* __restrict__ bq,
                 const float* __restrict__ wk, const float* __restrict__ bk,
                 const float* __restrict__ wv, const float* __restrict__ bv,
                 const float* __restrict__ cs, const float* __restrict__ sn,
                 float* __restrict__ outw)
{
    __shared__ unsigned As[128*36];   // [m][k] ld 36
    __shared__ unsigned Bs[64*36];    // [n][k] ld 36 (transposed)

    const int tid  = threadIdx.x;
    const int lane = tid & 31, warp = tid >> 5;
    const int wm = warp >> 1, wn = warp & 1;
    const int gr = lane >> 2, tg = lane & 3;
    const int n0 = blockIdx.x * 64;
    const int m0 = blockIdx.y * 128;

    const float* W; const float* bias = bq; int ldw, col0;
    if (MODE == 0) {
        if (n0 < 896)       { W = wq; bias = bq; ldw = 896; col0 = n0;        }
        else if (n0 < 1024) { W = wk; bias = bk; ldw = 128; col0 = n0 - 896;  }
        else                { W = wv; bias = bv; ldw = 128; col0 = n0 - 1024; }
    } else {
        W = wq; ldw = 896; col0 = n0;
    }
    const float* Ap = (MODE == 1) ? (const float*)g_att : Aa;

    float acc[2][4][4];
    #pragma unroll
    for (int mt = 0; mt < 2; mt++)
        #pragma unroll
        for (int nt = 0; nt < 4; nt++)
            #pragma unroll
            for (int j = 0; j < 4; j++) acc[mt][nt][j] = 0.f;

    const int ar = tid >> 3, ac = (tid & 7) * 4;   // A staging
    const int bn  = tid & 63;                      // B staging: one n-row
    const int bkg = (tid >> 6) * 8;                //   8 consecutive k's
    const int lrow = (lane & 7) + ((lane >> 3) & 1) * 8;
    const int lg   = (lane >> 4) * 4;
    const int brow = lane & 7;
    const int bg4  = (lane >> 3) * 4;

    // preload chunk 0 into registers (MODE 1: A is already tf32 bits)
    float4 na[4];
    uint4  na_b[4];
    float  nbv[8];
    #pragma unroll
    for (int r = 0; r < 4; r++) {
        if (MODE == 0)
            na[r]   = *(const float4*)(Ap + (size_t)(m0 + ar + r*32)*C_ + ac);
        else
            na_b[r] = *(const uint4*)(Ap + (size_t)(m0 + ar + r*32)*C_ + ac);
    }
    #pragma unroll
    for (int i = 0; i < 8; i++)
        nbv[i] = W[(size_t)(bkg + i)*ldw + col0 + bn];

    for (int k0 = 0; k0 < C_; k0 += 32) {
        #pragma unroll
        for (int r = 0; r < 4; r++) {
            if (MODE == 0)
                *(uint4*)(As + (ar + r*32)*36 + ac) =
                    make_uint4(f2tf(na[r].x), f2tf(na[r].y), f2tf(na[r].z), f2tf(na[r].w));
            else
                *(uint4*)(As + (ar + r*32)*36 + ac) = na_b[r];
        }
        *(uint4*)(Bs + bn*36 + bkg) =
            make_uint4(f2tf(nbv[0]), f2tf(nbv[1]), f2tf(nbv[2]), f2tf(nbv[3]));
        *(uint4*)(Bs + bn*36 + bkg + 4) =
            make_uint4(f2tf(nbv[4]), f2tf(nbv[5]), f2tf(nbv[6]), f2tf(nbv[7]));
        __syncthreads();

        if (k0 + 32 < C_) {
            #pragma unroll
            for (int r = 0; r < 4; r++) {
                if (MODE == 0)
                    na[r]   = *(const float4*)(Ap + (size_t)(m0 + ar + r*32)*C_ + k0 + 32 + ac);
                else
                    na_b[r] = *(const uint4*)(Ap + (size_t)(m0 + ar + r*32)*C_ + k0 + 32 + ac);
            }
            #pragma unroll
            for (int i = 0; i < 8; i++)
                nbv[i] = W[(size_t)(k0 + 32 + bkg + i)*ldw + col0 + bn];
        }

        #pragma unroll
        for (int kcp = 0; kcp < 2; kcp++) {
            unsigned aF[2][2][4];
            #pragma unroll
            for (int mt = 0; mt < 2; mt++)
                #pragma unroll
                for (int kk = 0; kk < 2; kk++) {
                    unsigned ad = sptr(As + (wm*32 + mt*16 + lrow)*36
                                       + (kcp*2 + kk)*8 + lg);
                    ldsm4(aF[mt][kk][0], aF[mt][kk][1], aF[mt][kk][2], aF[mt][kk][3], ad);
                }
            unsigned bF[4][4];
            #pragma unroll
            for (int nt = 0; nt < 4; nt++) {
                unsigned ad = sptr(Bs + (ncol_map(wn, nt) + brow)*36 + kcp*16 + bg4);
                ldsm4(bF[nt][0], bF[nt][1], bF[nt][2], bF[nt][3], ad);
            }
            #pragma unroll
            for (int nt = 0; nt < 4; nt++) {
                mma_tf32(acc[0][nt], aF[0][0], bF[nt][0], bF[nt][1]);
                mma_tf32(acc[0][nt], aF[0][1], bF[nt][2], bF[nt][3]);
                mma_tf32(acc[1][nt], aF[1][0], bF[nt][0], bF[nt][1]);
                mma_tf32(acc[1][nt], aF[1][1], bF[nt][2], bF[nt][3]);
            }
        }
        __syncthreads();
    }

    if (MODE == 0) {
        const bool is_q = (n0 < 896);
        const bool is_k = (n0 >= 896 && n0 < 1024);
        const int head = col0 >> 6;
        const float QSC = 0.125f * 1.4426950408889634f;
        #pragma unroll
        for (int mt = 0; mt < 2; mt++) {
            #pragma unroll
            for (int half = 0; half < 2; half++) {
                const int m = m0 + wm*32 + mt*16 + gr + half*8;
                const int bb = m >> 11, t = m & (T_-1);
                if (is_q || is_k) {
                    float* base = (is_q ? g_q : g_k)
                        + (((size_t)(bb*(is_q ? H_ : HKV_) + head))*T_ + t)*D_;
                    const float sc = is_q ? QSC : 1.0f;
                    #pragma unroll
                    for (int nt = 0; nt < 2; nt++) {
                        const int p = wn*16 + nt*8 + tg*2;   // 0..30
                        float2 c2 = *(const float2*)(cs + (size_t)t*D_ + p);
                        float2 s2 = *(const float2*)(sn + (size_t)t*D_ + p);
                        float lox = acc[mt][nt  ][half*2+0] + bias[col0 + p];
                        float loy = acc[mt][nt  ][half*2+1] + bias[col0 + p + 1];
                        float hix = acc[mt][nt+2][half*2+0] + bias[col0 + p + 32];
                        float hiy = acc[mt][nt+2][half*2+1] + bias[col0 + p + 33];
                        uint2 ulo, uhi;
                        ulo.x = f2tf((lox*c2.x - hix*s2.x) * sc);
                        ulo.y = f2tf((loy*c2.y - hiy*s2.y) * sc);
                        uhi.x = f2tf((hix*c2.x + lox*s2.x) * sc);
                        uhi.y = f2tf((hiy*c2.y + loy*s2.y) * sc);
                        *(uint2*)(base + p)      = ulo;
                        *(uint2*)(base + p + 32) = uhi;
                    }
                } else {
                    // V: transposed + key-permuted tf32 bits -> g_vT[b,hkv,d,t']
                    const int tp = (t & ~7) | ((t >> 1) & 3) | ((t & 1) << 2);
                    unsigned* gv = g_vT + ((size_t)(bb*HKV_ + head))*D_*T_;
                    #pragma unroll
                    for (int nt = 0; nt < 4; nt++) {
                        const int d = ncol_map(wn, nt) + tg*2;
                        gv[(size_t)d*T_ + tp]     = f2tf(acc[mt][nt][half*2+0] + bias[col0 + d]);
                        gv[(size_t)(d+1)*T_ + tp] = f2tf(acc[mt][nt][half*2+1] + bias[col0 + d + 1]);
                    }
                }
            }
        }
    } else {
        #pragma unroll
        for (int mt = 0; mt < 2; mt++) {
            #pragma unroll
            for (int half = 0; half < 2; half++) {
                const int m = m0 + wm*32 + mt*16 + gr + half*8;
                #pragma unroll
                for (int nt = 0; nt < 4; nt++) {
                    const int nl = ncol_map(wn, nt) + tg*2;
                    float2 v;
                    v.x = acc[mt][nt][half*2 + 0];
                    v.y = acc[mt][nt][half*2 + 1];
                    *(float2*)(outw + (size_t)m*C_ + n0 + nl) = v;
                }
            }
        }
    }
}

// =====================================================================
// Flash attention (R14 base): 128-row q-tile, 4 warps x m32, K/V
// DOUBLE-buffered.  ALL staging now via cp.async: Q,K row-major bits,
// V from g_vT (already transposed + key-permuted).  Q A-fragments
// hoisted to registers, permuted-V direct-A PV, ex2 softmax.
// Smem words: 128*68 + 2*64*68 + 2*64*68 = 26112 (102KB).
// =====================================================================
#define QS_OFF       0
#define KS_OFF(buf)  (8704 + (buf)*4352)
#define VT_OFF(buf)  (17408 + (buf)*4352)

__global__ __launch_bounds__(128)
void attn_kernel()
{
    extern __shared__ unsigned sm[];

    const int tid  = threadIdx.x;
    const int lane = tid & 31, warp = tid >> 5;
    const int gr = lane >> 2, tg = lane & 3;
    const int qi = (T_/128 - 1) - blockIdx.x;     // LPT: heaviest first
    const int h  = blockIdx.y;
    const int b  = blockIdx.z;
    const int hkv = h / REP_;

    const float*    Q     = g_q  + (((size_t)(b*H_ + h))*T_ + qi*128)*D_;
    const float*    Kbase = g_k  + ((size_t)(b*HKV_ + hkv))*T_*D_;
    const unsigned* Vbase = g_vT + ((size_t)(b*HKV_ + hkv))*D_*T_;

    const int srow = tid & 63;
    const int sdh  = (tid >> 6) * 32;
    const int lrow = (lane & 7) + ((lane >> 3) & 1) * 8;
    const int lg4  = (lane >> 4) * 4;
    const int brow = lane & 7;
    const int bg4  = (lane >> 3) * 4;

    // ---- stage Q (tf32 bits, pre-scaled): own cp.async group ----
    #pragma unroll
    for (int g = 0; g < 16; g++)
        cpasync16(sptr(sm + QS_OFF + tid*68 + g*4), Q + (size_t)tid*D_ + g*4);
    CP_COMMIT();

    float o[2][8][4];
    float s[2][8][4];
    #pragma unroll
    for (int mf = 0; mf < 2; mf++)
        #pragma unroll
        for (int nt = 0; nt < 8; nt++)
            #pragma unroll
            for (int j = 0; j < 4; j++) o[mf][nt][j] = 0.f;
    float mrow[2][2] = {{-1e30f,-1e30f},{-1e30f,-1e30f}};
    float lrw[2][2]  = {{0.f,0.f},{0.f,0.f}};

    // ---- stage K/V tile 0 into buf 0 (all cp.async) ----
    #pragma unroll
    for (int g = 0; g < 8; g++)
        cpasync16(sptr(sm + KS_OFF(0) + srow*68 + sdh + g*4),
                  Kbase + (size_t)srow*D_ + sdh + g*4);
    #pragma unroll
    for (int g = 0; g < 8; g++)
        cpasync16(sptr(sm + VT_OFF(0) + srow*68 + sdh + g*4),
                  Vbase + (size_t)srow*T_ + sdh + g*4);
    CP_COMMIT();

    const int warpm = warp * 32;

    // ---- hoist Q A-fragments to registers (loop-invariant) ----
    unsigned QA[8][2][4];   // [kchunk][mf][frag]
    CP_WAIT1();             // Q group complete (K/V group may be in flight)
    __syncthreads();
    #pragma unroll
    for (int kc = 0; kc < 8; kc++) {
        #pragma unroll
        for (int mf = 0; mf < 2; mf++) {
            unsigned ad = sptr(sm + QS_OFF + (warpm + mf*16 + lrow)*68 + kc*8 + lg4);
            ldsm4(QA[kc][mf][0], QA[kc][mf][1], QA[kc][mf][2], QA[kc][mf][3], ad);
        }
    }

    const int ktmax = 2*qi + 1;

    for (int kt = 0; kt <= ktmax; kt++) {
        CP_WAIT0();
        __syncthreads();
        if (kt < ktmax) {  // prefetch next tile (all cp.async)
            const int nb = (kt + 1) & 1;
            #pragma unroll
            for (int g = 0; g < 8; g++)
                cpasync16(sptr(sm + KS_OFF(nb) + srow*68 + sdh + g*4),
                          Kbase + (size_t)((kt+1)*64 + srow)*D_ + sdh + g*4);
            #pragma unroll
            for (int g = 0; g < 8; g++)
                cpasync16(sptr(sm + VT_OFF(nb) + srow*68 + sdh + g*4),
                          Vbase + (size_t)srow*T_ + (kt+1)*64 + sdh + g*4);
            CP_COMMIT();
        }
        const unsigned* Ksb = sm + KS_OFF(kt & 1);
        const unsigned* Vtb = sm + VT_OFF(kt & 1);

        // ---- S = (Q*sc) @ K^T  (A-fragments from registers) ----
        #pragma unroll
        for (int mf = 0; mf < 2; mf++)
            #pragma unroll
            for (int nt = 0; nt < 8; nt++)
                #pragma unroll
                for (int j = 0; j < 4; j++) s[mf][nt][j] = 0.f;

        #pragma unroll
        for (int kcp = 0; kcp < 4; kcp++) {
            #pragma unroll
            for (int nt = 0; nt < 8; nt++) {
                unsigned b0, b1, b2, b3;
                unsigned ad = sptr(Ksb + (nt*8 + brow)*68 + kcp*16 + bg4);
                ldsm4(b0, b1, b2, b3, ad);
                mma_tf32(s[0][nt], QA[2*kcp    ][0], b0, b1);
                mma_tf32(s[0][nt], QA[2*kcp + 1][0], b2, b3);
                mma_tf32(s[1][nt], QA[2*kcp    ][1], b0, b1);
                mma_tf32(s[1][nt], QA[2*kcp + 1][1], b2, b3);
            }
        }

        // ---- online softmax (ex2 domain) ----
        const bool diag = (kt >= 2*qi);
        #pragma unroll
        for (int mf = 0; mf < 2; mf++) {
            #pragma unroll
            for (int half = 0; half < 2; half++) {
                float mx = -1e30f;
                if (diag) {
                    const int grow = qi*128 + warpm + mf*16 + gr + half*8;
                    #pragma unroll
                    for (int nt = 0; nt < 8; nt++) {
                        #pragma unroll
                        for (int j = 0; j < 2; j++) {
                            float v = s[mf][nt][half*2 + j];
                            if (kt*64 + nt*8 + tg*2 + j > grow) v = -1e30f;
                            s[mf][nt][half*2 + j] = v;
                            mx = fmaxf(mx, v);
                        }
                    }
                } else {
                    #pragma unroll
                    for (int nt = 0; nt < 8; nt++)
                        mx = fmaxf(mx, fmaxf(s[mf][nt][half*2], s[mf][nt][half*2 + 1]));
                }
                mx = fmaxf(mx, __shfl_xor_sync(0xffffffffu, mx, 1));
                mx = fmaxf(mx, __shfl_xor_sync(0xffffffffu, mx, 2));
                const float newm  = fmaxf(mrow[mf][half], mx);
                const float alpha = ex2f(mrow[mf][half] - newm);
                mrow[mf][half] = newm;
                float rs = 0.f;
                #pragma unroll
                for (int nt = 0; nt < 8; nt++) {
                    #pragma unroll
                    for (int j = 0; j < 2; j++) {
                        float p = ex2f(s[mf][nt][half*2 + j] - newm);
                        s[mf][nt][half*2 + j] = p;
                        rs += p;
                    }
                }
                rs += __shfl_xor_sync(0xffffffffu, rs, 1);
                rs += __shfl_xor_sync(0xffffffffu, rs, 2);
                lrw[mf][half] = lrw[mf][half]*alpha + rs;
                #pragma unroll
                for (int nt = 0; nt < 8; nt++) {
                    o[mf][nt][half*2 + 0] *= alpha;
                    o[mf][nt][half*2 + 1] *= alpha;
                }
            }
        }

        // ---- O += P @ V  (S accumulator used directly as A-fragment;
        //      V pre-permuted in g_vT) ----
        #pragma unroll
        for (int kcp = 0; kcp < 4; kcp++) {
            unsigned A[2][2][4];
            #pragma unroll
            for (int mf = 0; mf < 2; mf++)
                #pragma unroll
                for (int kk = 0; kk < 2; kk++) {
                    const float* sv = s[mf][2*kcp + kk];
                    A[mf][kk][0] = f2tf(sv[0]);
                    A[mf][kk][1] = f2tf(sv[2]);
                    A[mf][kk][2] = f2tf(sv[1]);
                    A[mf][kk][3] = f2tf(sv[3]);
                }
            #pragma unroll
            for (int nt = 0; nt < 8; nt++) {
                unsigned b0, b1, b2, b3;
                unsigned ad = sptr(Vtb + (nt*8 + brow)*68 + kcp*16 + bg4);
                ldsm4(b0, b1, b2, b3, ad);
                mma_tf32(o[0][nt], A[0][0], b0, b1);
                mma_tf32(o[0][nt], A[0][1], b2, b3);
                mma_tf32(o[1][nt], A[1][0], b0, b1);
                mma_tf32(o[1][nt], A[1][1], b2, b3);
            }
        }
    }

    // ---- epilogue: store tf32 BITS to g_att (gemm1 reads bits) ----
    #pragma unroll
    for (int mf = 0; mf < 2; mf++) {
        const float inv0 = 1.f / lrw[mf][0];
        const float inv1 = 1.f / lrw[mf][1];
        const int t0 = qi*128 + warpm + mf*16 + gr;
        #pragma unroll
        for (int nt = 0; nt < 8; nt++) {
            const int col = h*64 + nt*8 + tg*2;
            uint2 u0, u1;
            u0.x = f2tf(o[mf][nt][0]*inv0); u0.y = f2tf(o[mf][nt][1]*inv0);
            u1.x = f2tf(o[mf][nt][2]*inv1); u1.y = f2tf(o[mf][nt][3]*inv1);
            *(uint2*)(g_att + ((size_t)b*T_ + t0    )*C_ + col) = u0;
            *(uint2*)(g_att + ((size_t)b*T_ + t0 + 8)*C_ + col) = u1;
        }
    }
}

// =====================================================================
extern "C" void kernel_launch(void* const* d_in, const int* in_sizes, int n_in,
                              void* d_out, int out_size)
{
    const float* x  = (const float*)d_in[0];
    const float* wq = (const float*)d_in[1];
    const float* bq = (const float*)d_in[2];
    const float* wk = (const float*)d_in[3];
    const float* bk = (const float*)d_in[4];
    const float* wv = (const float*)d_in[5];
    const float* bv = (const float*)d_in[6];
    const float* wo = (const float*)d_in[7];
    const float* cs = (const float*)d_in[8];
    const float* sn = (const float*)d_in[9];
    float* out = (float*)d_out;

    const int ATTN_SMEM = 26112 * 4;   // 104448 B
    static int configured = 0;
    if (!configured) {
        cudaFuncSetAttribute(attn_kernel,
                             cudaFuncAttributeMaxDynamicSharedMemorySize, ATTN_SMEM);
        configured = 1;
    }

    gemm_kernel<0><<<dim3(18, 32), 256>>>(x, wq, bq, wk, bk, wv, bv, cs, sn, nullptr);

    attn_kernel<<<dim3(T_/128, H_, B_), 128, ATTN_SMEM>>>();

    gemm_kernel<1><<<dim3(14, 32), 256>>>(nullptr, wo, nullptr, nullptr, nullptr,
                                          nullptr, nullptr, nullptr, nullptr, out);
}

// round 17
// speedup vs baseline: 1.1398x; 1.1398x over previous
#include <cuda_runtime.h>
#include <math.h>

#define B_   2
#define T_   2048
#define C_   896
#define H_   14
#define HKV_ 2
#define D_   64
#define M_   (B_*T_)          // 4096
#define REP_ (H_/HKV_)        // 7

// ---------------- static scratch ----------------
// g_q: tf32 bits pre-scaled by 0.125*log2(e); g_k/g_v: tf32 bits.
// g_att: tf32 bits (converted in attn epilogue for gemm1).
__device__ float g_q[(size_t)B_*H_*T_*D_];     // [B,H,T,D]
__device__ float g_k[(size_t)B_*HKV_*T_*D_];   // [B,HKV,T,D]
__device__ float g_v[(size_t)B_*HKV_*T_*D_];   // [B,HKV,T,D]
__device__ float g_att[(size_t)B_*T_*C_];      // [B,T,H*D] tf32 bits

// ---------------- helpers ----------------
__device__ __forceinline__ unsigned f2tf(float f) {
    unsigned u;
    asm("cvt.rna.tf32.f32 %0, %1;" : "=r"(u) : "f"(f));
    return u;
}
__device__ __forceinline__ float ex2f(float x) {
    float r;
    asm("ex2.approx.f32 %0, %1;" : "=f"(r) : "f"(x));
    return r;
}
__device__ __forceinline__ unsigned sptr(const void* p) {
    return (unsigned)__cvta_generic_to_shared(p);
}
__device__ __forceinline__ void cpasync16(unsigned smem_addr, const void* gptr) {
    asm volatile("cp.async.cg.shared.global [%0], [%1], 16;"
                 :: "r"(smem_addr), "l"(gptr));
}
#define CP_COMMIT() asm volatile("cp.async.commit_group;" ::: "memory")
#define CP_WAIT0()  asm volatile("cp.async.wait_group 0;" ::: "memory")
#define CP_WAIT1()  asm volatile("cp.async.wait_group 1;" ::: "memory")

__device__ __forceinline__ void ldsm4(unsigned& r0, unsigned& r1,
                                      unsigned& r2, unsigned& r3, unsigned a) {
    asm volatile("ldmatrix.sync.aligned.m8n8.x4.shared.b16 {%0,%1,%2,%3}, [%4];"
                 : "=r"(r0), "=r"(r1), "=r"(r2), "=r"(r3) : "r"(a));
}
__device__ __forceinline__ void mma_tf32(float c[4],
                                         const unsigned a[4],
                                         unsigned b0, unsigned b1)
{
    asm volatile("mma.sync.aligned.m16n8k8.row.col.f32.tf32.tf32.f32 "
                 "{%0,%1,%2,%3}, {%4,%5,%6,%7}, {%8,%9}, {%0,%1,%2,%3};"
                 : "+f"(c[0]), "+f"(c[1]), "+f"(c[2]), "+f"(c[3])
                 : "r"(a[0]), "r"(a[1]), "r"(a[2]), "r"(a[3]), "r"(b0), "r"(b1));
}

// warp n-column map: warp wn owns cols {wn*16..+15} U {32+wn*16..+15}
__device__ __forceinline__ int ncol_map(int wn, int nt) {
    return wn*16 + (nt & 1)*8 + (nt >> 1)*32;
}

// =====================================================================
// GEMM kernel (R14, unchanged).
// MODE 0 = QKV proj, fused bias + RoPE; q/k/v stored as TF32 BITS
//          (q pre-scaled by 0.125*log2e) for the attention kernel.
// MODE 1 = WO (A = g_att tf32 BITS; fp32 out).
// =====================================================================
template<int MODE>
__global__ __launch_bounds__(256, 2)
void gemm_kernel(const float* __restrict__ Aa,
                 const float* __restrict__ wq, const float* __restrict__ bq,
                 const float* __restrict__ wk, const float* __restrict__ bk,
                 const float* __restrict__ wv, const float* __restrict__ bv,
                 const float* __restrict__ cs, const float* __restrict__ sn,
                 float* __restrict__ outw)
{
    __shared__ unsigned As[128*36];   // [m][k] ld 36
    __shared__ unsigned Bs[64*36];    // [n][k] ld 36 (transposed)

    const int tid  = threadIdx.x;
    const int lane = tid & 31, warp = tid >> 5;
    const int wm = warp >> 1, wn = warp & 1;
    const int gr = lane >> 2, tg = lane & 3;
    const int n0 = blockIdx.x * 64;
    const int m0 = blockIdx.y * 128;

    const float* W; const float* bias = bq; int ldw, col0;
    if (MODE == 0) {
        if (n0 < 896)       { W = wq; bias = bq; ldw = 896; col0 = n0;        }
        else if (n0 < 1024) { W = wk; bias = bk; ldw = 128; col0 = n0 - 896;  }
        else                { W = wv; bias = bv; ldw = 128; col0 = n0 - 1024; }
    } else {
        W = wq; ldw = 896; col0 = n0;
    }
    const float* Ap = (MODE == 1) ? (const float*)g_att : Aa;

    float acc[2][4][4];
    #pragma unroll
    for (int mt = 0; mt < 2; mt++)
        #pragma unroll
        for (int nt = 0; nt < 4; nt++)
            #pragma unroll
            for (int j = 0; j < 4; j++) acc[mt][nt][j] = 0.f;

    const int ar = tid >> 3, ac = (tid & 7) * 4;   // A staging
    const int bn  = tid & 63;                      // B staging: one n-row
    const int bkg = (tid >> 6) * 8;                //   8 consecutive k's
    const int lrow = (lane & 7) + ((lane >> 3) & 1) * 8;
    const int lg   = (lane >> 4) * 4;
    const int brow = lane & 7;
    const int bg4  = (lane >> 3) * 4;

    // preload chunk 0 into registers (MODE 1: A is already tf32 bits)
    float4 na[4];
    uint4  na_b[4];
    float  nbv[8];
    #pragma unroll
    for (int r = 0; r < 4; r++) {
        if (MODE == 0)
            na[r]   = *(const float4*)(Ap + (size_t)(m0 + ar + r*32)*C_ + ac);
        else
            na_b[r] = *(const uint4*)(Ap + (size_t)(m0 + ar + r*32)*C_ + ac);
    }
    #pragma unroll
    for (int i = 0; i < 8; i++)
        nbv[i] = W[(size_t)(bkg + i)*ldw + col0 + bn];

    for (int k0 = 0; k0 < C_; k0 += 32) {
        #pragma unroll
        for (int r = 0; r < 4; r++) {
            if (MODE == 0)
                *(uint4*)(As + (ar + r*32)*36 + ac) =
                    make_uint4(f2tf(na[r].x), f2tf(na[r].y), f2tf(na[r].z), f2tf(na[r].w));
            else
                *(uint4*)(As + (ar + r*32)*36 + ac) = na_b[r];
        }
        *(uint4*)(Bs + bn*36 + bkg) =
            make_uint4(f2tf(nbv[0]), f2tf(nbv[1]), f2tf(nbv[2]), f2tf(nbv[3]));
        *(uint4*)(Bs + bn*36 + bkg + 4) =
            make_uint4(f2tf(nbv[4]), f2tf(nbv[5]), f2tf(nbv[6]), f2tf(nbv[7]));
        __syncthreads();

        if (k0 + 32 < C_) {
            #pragma unroll
            for (int r = 0; r < 4; r++) {
                if (MODE == 0)
                    na[r]   = *(const float4*)(Ap + (size_t)(m0 + ar + r*32)*C_ + k0 + 32 + ac);
                else
                    na_b[r] = *(const uint4*)(Ap + (size_t)(m0 + ar + r*32)*C_ + k0 + 32 + ac);
            }
            #pragma unroll
            for (int i = 0; i < 8; i++)
                nbv[i] = W[(size_t)(k0 + 32 + bkg + i)*ldw + col0 + bn];
        }

        #pragma unroll
        for (int kcp = 0; kcp < 2; kcp++) {
            unsigned aF[2][2][4];
            #pragma unroll
            for (int mt = 0; mt < 2; mt++)
                #pragma unroll
                for (int kk = 0; kk < 2; kk++) {
                    unsigned ad = sptr(As + (wm*32 + mt*16 + lrow)*36
                                       + (kcp*2 + kk)*8 + lg);
                    ldsm4(aF[mt][kk][0], aF[mt][kk][1], aF[mt][kk][2], aF[mt][kk][3], ad);
                }
            unsigned bF[4][4];
            #pragma unroll
            for (int nt = 0; nt < 4; nt++) {
                unsigned ad = sptr(Bs + (ncol_map(wn, nt) + brow)*36 + kcp*16 + bg4);
                ldsm4(bF[nt][0], bF[nt][1], bF[nt][2], bF[nt][3], ad);
            }
            #pragma unroll
            for (int nt = 0; nt < 4; nt++) {
                mma_tf32(acc[0][nt], aF[0][0], bF[nt][0], bF[nt][1]);
                mma_tf32(acc[0][nt], aF[0][1], bF[nt][2], bF[nt][3]);
                mma_tf32(acc[1][nt], aF[1][0], bF[nt][0], bF[nt][1]);
                mma_tf32(acc[1][nt], aF[1][1], bF[nt][2], bF[nt][3]);
            }
        }
        __syncthreads();
    }

    if (MODE == 0) {
        float* outb; int nheads;
        if (n0 < 896)       { outb = g_q; nheads = H_;   }
        else if (n0 < 1024) { outb = g_k; nheads = HKV_; }
        else                { outb = g_v; nheads = HKV_; }
        const int head = col0 >> 6;
        const bool do_rope = (n0 < 1024);
        const bool is_q    = (n0 < 896);
        const float QSC = 0.125f * 1.4426950408889634f;
        #pragma unroll
        for (int mt = 0; mt < 2; mt++) {
            #pragma unroll
            for (int half = 0; half < 2; half++) {
                const int m = m0 + wm*32 + mt*16 + gr + half*8;
                const int bb = m >> 11, t = m & (T_-1);
                float* base = outb + (((size_t)(bb*nheads + head))*T_ + t)*D_;
                if (do_rope) {
                    const float sc = is_q ? QSC : 1.0f;
                    #pragma unroll
                    for (int nt = 0; nt < 2; nt++) {
                        const int p = wn*16 + nt*8 + tg*2;   // 0..30
                        float2 c2 = *(const float2*)(cs + (size_t)t*D_ + p);
                        float2 s2 = *(const float2*)(sn + (size_t)t*D_ + p);
                        float lox = acc[mt][nt  ][half*2+0] + bias[col0 + p];
                        float loy = acc[mt][nt  ][half*2+1] + bias[col0 + p + 1];
                        float hix = acc[mt][nt+2][half*2+0] + bias[col0 + p + 32];
                        float hiy = acc[mt][nt+2][half*2+1] + bias[col0 + p + 33];
                        uint2 ulo, uhi;
                        ulo.x = f2tf((lox*c2.x - hix*s2.x) * sc);
                        ulo.y = f2tf((loy*c2.y - hiy*s2.y) * sc);
                        uhi.x = f2tf((hix*c2.x + lox*s2.x) * sc);
                        uhi.y = f2tf((hiy*c2.y + loy*s2.y) * sc);
                        *(uint2*)(base + p)      = ulo;
                        *(uint2*)(base + p + 32) = uhi;
                    }
                } else {
                    #pragma unroll
                    for (int nt = 0; nt < 4; nt++) {
                        const int nl = ncol_map(wn, nt) + tg*2;
                        uint2 u;
                        u.x = f2tf(acc[mt][nt][half*2 + 0] + bias[col0 + nl]);
                        u.y = f2tf(acc[mt][nt][half*2 + 1] + bias[col0 + nl + 1]);
                        *(uint2*)(base + nl) = u;
                    }
                }
            }
        }
    } else {
        #pragma unroll
        for (int mt = 0; mt < 2; mt++) {
            #pragma unroll
            for (int half = 0; half < 2; half++) {
                const int m = m0 + wm*32 + mt*16 + gr + half*8;
                #pragma unroll
                for (int nt = 0; nt < 4; nt++) {
                    const int nl = ncol_map(wn, nt) + tg*2;
                    float2 v;
                    v.x = acc[mt][nt][half*2 + 0];
                    v.y = acc[mt][nt][half*2 + 1];
                    *(float2*)(outw + (size_t)m*C_ + n0 + nl) = v;
                }
            }
        }
    }
}

// =====================================================================
// Flash attention (R14 inner loop, 2-PASS PAIRED SCHEDULING):
// block bx handles q-tiles (15-bx) then (bx) -> 34 k-tiles per block,
// 224 equal blocks = ONE balanced wave at 2 blocks/SM.
// 128-row q-tile, 4 warps x m32, K/V DOUBLE-buffered, Q/K cp.async,
// V transposed via LDG+STS, QA hoisted, permuted-V direct-A PV.
// Smem words: 128*68 + 2*64*68 + 2*64*68 = 26112 (102KB).
// =====================================================================
#define QS_OFF       0
#define KS_OFF(buf)  (8704 + (buf)*4352)
#define VT_OFF(buf)  (17408 + (buf)*4352)

__global__ __launch_bounds__(128)
void attn_kernel()
{
    extern __shared__ unsigned sm[];

    const int tid  = threadIdx.x;
    const int lane = tid & 31, warp = tid >> 5;
    const int gr = lane >> 2, tg = lane & 3;
    const int h  = blockIdx.y;
    const int b  = blockIdx.z;
    const int hkv = h / REP_;

    const float* Kbase = g_k + ((size_t)(b*HKV_ + hkv))*T_*D_;
    const float* Vbase = g_v + ((size_t)(b*HKV_ + hkv))*T_*D_;

    const int srow = tid & 63;
    const int sdh  = (tid >> 6) * 32;
    const int prow = (srow & ~7) | ((srow >> 1) & 3) | ((srow & 1) << 2);
    const int lrow = (lane & 7) + ((lane >> 3) & 1) * 8;
    const int lg4  = (lane >> 4) * 4;
    const int brow = lane & 7;
    const int bg4  = (lane >> 3) * 4;
    const int warpm = warp * 32;

    #pragma unroll 1
    for (int pass = 0; pass < 2; pass++) {
        const int qi = pass == 0 ? (15 - blockIdx.x) : blockIdx.x;
        const float* Q = g_q + (((size_t)(b*H_ + h))*T_ + qi*128)*D_;

        __syncthreads();   // prior pass done with all shared buffers

        // ---- stage Q (tf32 bits, pre-scaled): own cp.async group ----
        #pragma unroll
        for (int g = 0; g < 16; g++)
            cpasync16(sptr(sm + QS_OFF + tid*68 + g*4), Q + (size_t)tid*D_ + g*4);
        CP_COMMIT();

        float o[2][8][4];
        float s[2][8][4];
        #pragma unroll
        for (int mf = 0; mf < 2; mf++)
            #pragma unroll
            for (int nt = 0; nt < 8; nt++)
                #pragma unroll
                for (int j = 0; j < 4; j++) o[mf][nt][j] = 0.f;
        float mrow[2][2] = {{-1e30f,-1e30f},{-1e30f,-1e30f}};
        float lrw[2][2]  = {{0.f,0.f},{0.f,0.f}};

        // ---- stage K/V tile 0 into buf 0 ----
        #pragma unroll
        for (int g = 0; g < 8; g++)
            cpasync16(sptr(sm + KS_OFF(0) + srow*68 + sdh + g*4),
                      Kbase + (size_t)srow*D_ + sdh + g*4);
        {
            const uint4* vp = (const uint4*)(Vbase + (size_t)srow*D_ + sdh);
            unsigned* vt = sm + VT_OFF(0);
            #pragma unroll
            for (int g = 0; g < 8; g++) {
                uint4 vv = vp[g];
                const int d0 = sdh + g*4;
                vt[(d0+0)*68 + prow] = vv.x;
                vt[(d0+1)*68 + prow] = vv.y;
                vt[(d0+2)*68 + prow] = vv.z;
                vt[(d0+3)*68 + prow] = vv.w;
            }
        }
        CP_COMMIT();

        // ---- hoist Q A-fragments to registers (loop-invariant) ----
        unsigned QA[8][2][4];   // [kchunk][mf][frag]
        CP_WAIT1();             // Q group complete (K/V group may be in flight)
        __syncthreads();
        #pragma unroll
        for (int kc = 0; kc < 8; kc++) {
            #pragma unroll
            for (int mf = 0; mf < 2; mf++) {
                unsigned ad = sptr(sm + QS_OFF + (warpm + mf*16 + lrow)*68 + kc*8 + lg4);
                ldsm4(QA[kc][mf][0], QA[kc][mf][1], QA[kc][mf][2], QA[kc][mf][3], ad);
            }
        }

        const int ktmax = 2*qi + 1;

        for (int kt = 0; kt <= ktmax; kt++) {
            CP_WAIT0();
            __syncthreads();
            if (kt < ktmax) {  // prefetch next tile
                const int nb = (kt + 1) & 1;
                #pragma unroll
                for (int g = 0; g < 8; g++)
                    cpasync16(sptr(sm + KS_OFF(nb) + srow*68 + sdh + g*4),
                              Kbase + (size_t)((kt+1)*64 + srow)*D_ + sdh + g*4);
                const uint4* vp = (const uint4*)(Vbase + (size_t)((kt+1)*64 + srow)*D_ + sdh);
                unsigned* vt = sm + VT_OFF(nb);
                #pragma unroll
                for (int g = 0; g < 8; g++) {
                    uint4 vv = vp[g];
                    const int d0 = sdh + g*4;
                    vt[(d0+0)*68 + prow] = vv.x;
                    vt[(d0+1)*68 + prow] = vv.y;
                    vt[(d0+2)*68 + prow] = vv.z;
                    vt[(d0+3)*68 + prow] = vv.w;
                }
                CP_COMMIT();
            }
            const unsigned* Ksb = sm + KS_OFF(kt & 1);
            const unsigned* Vtb = sm + VT_OFF(kt & 1);

            // ---- S = (Q*sc) @ K^T  (A-fragments from registers) ----
            #pragma unroll
            for (int mf = 0; mf < 2; mf++)
                #pragma unroll
                for (int nt = 0; nt < 8; nt++)
                    #pragma unroll
                    for (int j = 0; j < 4; j++) s[mf][nt][j] = 0.f;

            #pragma unroll
            for (int kcp = 0; kcp < 4; kcp++) {
                #pragma unroll
                for (int nt = 0; nt < 8; nt++) {
                    unsigned b0, b1, b2, b3;
                    unsigned ad = sptr(Ksb + (nt*8 + brow)*68 + kcp*16 + bg4);
                    ldsm4(b0, b1, b2, b3, ad);
                    mma_tf32(s[0][nt], QA[2*kcp    ][0], b0, b1);
                    mma_tf32(s[0][nt], QA[2*kcp + 1][0], b2, b3);
                    mma_tf32(s[1][nt], QA[2*kcp    ][1], b0, b1);
                    mma_tf32(s[1][nt], QA[2*kcp + 1][1], b2, b3);
                }
            }

            // ---- online softmax (ex2 domain) ----
            const bool diag = (kt >= 2*qi);
            #pragma unroll
            for (int mf = 0; mf < 2; mf++) {
                #pragma unroll
                for (int half = 0; half < 2; half++) {
                    float mx = -1e30f;
                    if (diag) {
                        const int grow = qi*128 + warpm + mf*16 + gr + half*8;
                        #pragma unroll
                        for (int nt = 0; nt < 8; nt++) {
                            #pragma unroll
                            for (int j = 0; j < 2; j++) {
                                float v = s[mf][nt][half*2 + j];
                                if (kt*64 + nt*8 + tg*2 + j > grow) v = -1e30f;
                                s[mf][nt][half*2 + j] = v;
                                mx = fmaxf(mx, v);
                            }
                        }
                    } else {
                        #pragma unroll
                        for (int nt = 0; nt < 8; nt++)
                            mx = fmaxf(mx, fmaxf(s[mf][nt][half*2], s[mf][nt][half*2 + 1]));
                    }
                    mx = fmaxf(mx, __shfl_xor_sync(0xffffffffu, mx, 1));
                    mx = fmaxf(mx, __shfl_xor_sync(0xffffffffu, mx, 2));
                    const float newm  = fmaxf(mrow[mf][half], mx);
                    const float alpha = ex2f(mrow[mf][half] - newm);
                    mrow[mf][half] = newm;
                    float rs = 0.f;
                    #pragma unroll
                    for (int nt = 0; nt < 8; nt++) {
                        #pragma unroll
                        for (int j = 0; j < 2; j++) {
                            float p = ex2f(s[mf][nt][half*2 + j] - newm);
                            s[mf][nt][half*2 + j] = p;
                            rs += p;
                        }
                    }
                    rs += __shfl_xor_sync(0xffffffffu, rs, 1);
                    rs += __shfl_xor_sync(0xffffffffu, rs, 2);
                    lrw[mf][half] = lrw[mf][half]*alpha + rs;
                    #pragma unroll
                    for (int nt = 0; nt < 8; nt++) {
                        o[mf][nt][half*2 + 0] *= alpha;
                        o[mf][nt][half*2 + 1] *= alpha;
                    }
                }
            }

            // ---- O += P @ V  (S accumulator used directly as A-fragment;
            //      V staged with matching key permutation) ----
            #pragma unroll
            for (int kcp = 0; kcp < 4; kcp++) {
                unsigned A[2][2][4];
                #pragma unroll
                for (int mf = 0; mf < 2; mf++)
                    #pragma unroll
                    for (int kk = 0; kk < 2; kk++) {
                        const float* sv = s[mf][2*kcp + kk];
                        A[mf][kk][0] = f2tf(sv[0]);
                        A[mf][kk][1] = f2tf(sv[2]);
                        A[mf][kk][2] = f2tf(sv[1]);
                        A[mf][kk][3] = f2tf(sv[3]);
                    }
                #pragma unroll
                for (int nt = 0; nt < 8; nt++) {
                    unsigned b0, b1, b2, b3;
                    unsigned ad = sptr(Vtb + (nt*8 + brow)*68 + kcp*16 + bg4);
                    ldsm4(b0, b1, b2, b3, ad);
                    mma_tf32(o[0][nt], A[0][0], b0, b1);
                    mma_tf32(o[0][nt], A[0][1], b2, b3);
                    mma_tf32(o[1][nt], A[1][0], b0, b1);
                    mma_tf32(o[1][nt], A[1][1], b2, b3);
                }
            }
        }

        // ---- epilogue: store tf32 BITS to g_att (gemm1 reads bits) ----
        #pragma unroll
        for (int mf = 0; mf < 2; mf++) {
            const float inv0 = 1.f / lrw[mf][0];
            const float inv1 = 1.f / lrw[mf][1];
            const int t0 = qi*128 + warpm + mf*16 + gr;
            #pragma unroll
            for (int nt = 0; nt < 8; nt++) {
                const int col = h*64 + nt*8 + tg*2;
                uint2 u0, u1;
                u0.x = f2tf(o[mf][nt][0]*inv0); u0.y = f2tf(o[mf][nt][1]*inv0);
                u1.x = f2tf(o[mf][nt][2]*inv1); u1.y = f2tf(o[mf][nt][3]*inv1);
                *(uint2*)(g_att + ((size_t)b*T_ + t0    )*C_ + col) = u0;
                *(uint2*)(g_att + ((size_t)b*T_ + t0 + 8)*C_ + col) = u1;
            }
        }
    }
}

// =====================================================================
extern "C" void kernel_launch(void* const* d_in, const int* in_sizes, int n_in,
                              void* d_out, int out_size)
{
    const float* x  = (const float*)d_in[0];
    const float* wq = (const float*)d_in[1];
    const float* bq = (const float*)d_in[2];
    const float* wk = (const float*)d_in[3];
    const float* bk = (const float*)d_in[4];
    const float* wv = (const float*)d_in[5];
    const float* bv = (const float*)d_in[6];
    const float* wo = (const float*)d_in[7];
    const float* cs = (const float*)d_in[8];
    const float* sn = (const float*)d_in[9];
    float* out = (float*)d_out;

    const int ATTN_SMEM = 26112 * 4;   // 104448 B
    static int configured = 0;
    if (!configured) {
        cudaFuncSetAttribute(attn_kernel,
                             cudaFuncAttributeMaxDynamicSharedMemorySize, ATTN_SMEM);
        configured = 1;
    }

    gemm_kernel<0><<<dim3(18, 32), 256>>>(x, wq, bq, wk, bk, wv, bv, cs, sn, nullptr);

    attn_kernel<<<dim3(8, H_, B_), 128, ATTN_SMEM>>>();

    gemm_kernel<1><<<dim3(14, 32), 256>>>(nullptr, wo, nullptr, nullptr, nullptr,
                                          nullptr, nullptr, nullptr, nullptr, out);
}